// round 2
// baseline (speedup 1.0000x reference)
#include <cuda_runtime.h>
#include <math.h>

#define BB 64      // batch
#define EE 256     // embed
#define SS 32      // seq
#define HH 16      // heads
#define HD 16      // head dim
#define PP 512     // pairs
#define KC 46      // classes
#define MROWS (BB*SS)   // 2048
#define NCOLS (3*EE)    // 768

// ---------------- scratch (device globals; no allocation allowed) ----------
__device__ __align__(16) float g_QKV[MROWS * NCOLS];   // [m=b*32+s][n] n<256:Q, <512:K, <768:V
__device__ __align__(16) float g_O[BB * SS * EE];      // attention output per distinct i (=b)
__device__ __align__(16) float g_G[BB * EE];           // sum_s fw[s] * O[b,s,:]
__device__ __align__(16) float g_logprob[BB * KC];     // log_softmax(logits) per b
__device__ int   g_sel[PP];
__device__ int   g_i[PP], g_j[PP];
__device__ float g_valid[PP];
__device__ float g_cj[BB];

// ---------------- 1) pair setup: mask scan, sel, i/j, valid, c_j -----------
__global__ void pair_setup(const int* __restrict__ labels1) {
    __shared__ int l1[BB];
    __shared__ int cnt[256];
    __shared__ int off[257];
    __shared__ int cj[BB];
    int tid = threadIdx.x;
    if (tid < BB) { l1[tid] = labels1[tid]; cj[tid] = 0; }
    __syncthreads();
    int base = tid * 16;
    int c = 0;
    #pragma unroll
    for (int u = 0; u < 16; u++) {
        int idx = base + u;
        c += (l1[idx >> 6] == l1[idx & 63]);
    }
    cnt[tid] = c;
    __syncthreads();
    if (tid == 0) {
        int acc = 0;
        for (int t = 0; t < 256; t++) { off[t] = acc; acc += cnt[t]; }
        off[256] = acc;
    }
    __syncthreads();
    int pos = off[tid];
    #pragma unroll
    for (int u = 0; u < 16; u++) {
        int idx = base + u;
        if (l1[idx >> 6] == l1[idx & 63]) {
            if (pos < PP) g_sel[pos] = idx;
            pos++;
        }
    }
    int total = off[256];
    for (int p2 = total + tid; p2 < PP; p2 += 256) g_sel[p2] = 0;  // fill_value=0
    __syncthreads();
    int nv = total < PP ? total : PP;
    for (int p = tid; p < PP; p += 256) {
        int s0 = g_sel[p];
        int i = s0 >> 6, j = s0 & 63;
        g_i[p] = i; g_j[p] = j;
        g_valid[p] = (p < nv) ? 1.0f : 0.0f;
        atomicAdd(&cj[j], 1);    // counts over ALL P entries (fills included) — attention weights
    }
    __syncthreads();
    if (tid < BB) g_cj[tid] = (float)cj[tid];
}

// ---------------- 2) QKV projection GEMM: C[2048][768] = A @ W^T + b -------
// A[m][k] = feat[b, k, s]  (m = b*32+s), W = in_proj_w [768][256]
#define BM 64
#define BN 64
#define BK 16
__global__ void __launch_bounds__(256) qkv_gemm(const float* __restrict__ feat,
                                                const float* __restrict__ W,
                                                const float* __restrict__ bias) {
    __shared__ float As[BK][BM + 4];
    __shared__ float Bs[BK][BN + 4];
    int bm = blockIdx.x * BM, bn = blockIdx.y * BN;
    int tid = threadIdx.x;
    int tx = tid & 15, ty = tid >> 4;
    float acc[4][4] = {};
    for (int k0 = 0; k0 < EE; k0 += BK) {
        {   // A tile: 16k x 64m, 4 consecutive m per thread (contiguous s)
            int k  = tid >> 4;          // 0..15
            int m4 = (tid & 15) * 4;    // 0..60
            int m = bm + m4;
            int b = m >> 5, s = m & 31;
            float4 v = *(const float4*)(feat + b * (EE * SS) + (k0 + k) * SS + s);
            As[k][m4] = v.x; As[k][m4 + 1] = v.y; As[k][m4 + 2] = v.z; As[k][m4 + 3] = v.w;
        }
        {   // B tile: W[n][k], 4 consecutive k per thread, transpose into Bs[k][n]
            int n  = tid >> 2;          // 0..63
            int kk = (tid & 3) * 4;     // 0,4,8,12
            float4 v = *(const float4*)(W + (bn + n) * EE + k0 + kk);
            Bs[kk][n] = v.x; Bs[kk + 1][n] = v.y; Bs[kk + 2][n] = v.z; Bs[kk + 3][n] = v.w;
        }
        __syncthreads();
        #pragma unroll
        for (int k = 0; k < BK; k++) {
            float4 av = *(const float4*)&As[k][ty * 4];
            float4 bv = *(const float4*)&Bs[k][tx * 4];
            float a[4] = {av.x, av.y, av.z, av.w};
            float bb2[4] = {bv.x, bv.y, bv.z, bv.w};
            #pragma unroll
            for (int i = 0; i < 4; i++)
                #pragma unroll
                for (int j = 0; j < 4; j++)
                    acc[i][j] += a[i] * bb2[j];
        }
        __syncthreads();
    }
    #pragma unroll
    for (int i = 0; i < 4; i++) {
        int m = bm + ty * 4 + i;
        #pragma unroll
        for (int j = 0; j < 4; j++) {
            int n = bn + tx * 4 + j;
            g_QKV[m * NCOLS + n] = acc[i][j] + bias[n];
        }
    }
}

// ---------------- 3) attention per (s,h): count-weighted 64x64 softmax -----
__global__ void __launch_bounds__(64) attn_kernel() {
    int s = blockIdx.x & 31;
    int h = blockIdx.x >> 5;
    __shared__ float Ks[BB][HD];
    __shared__ float Vs[BB][HD];
    __shared__ float Ss[BB][BB + 1];
    __shared__ float cjs[BB];
    int b = threadIdx.x;   // 0..63, query row (distinct i)

    const float* qkv_row = g_QKV + (b * SS + s) * NCOLS + h * HD;
    {   // load K/V rows of this thread's b into smem
        const float4* kp = (const float4*)(qkv_row + EE);
        const float4* vp = (const float4*)(qkv_row + 2 * EE);
        float4* kd = (float4*)Ks[b];
        float4* vd = (float4*)Vs[b];
        kd[0] = kp[0]; kd[1] = kp[1]; kd[2] = kp[2]; kd[3] = kp[3];
        vd[0] = vp[0]; vd[1] = vp[1]; vd[2] = vp[2]; vd[3] = vp[3];
        cjs[b] = g_cj[b];
    }
    float4 q0 = ((const float4*)qkv_row)[0];
    float4 q1 = ((const float4*)qkv_row)[1];
    float4 q2 = ((const float4*)qkv_row)[2];
    float4 q3 = ((const float4*)qkv_row)[3];
    __syncthreads();

    float mx = -1e30f;
    #pragma unroll 4
    for (int j = 0; j < BB; j++) {
        const float4* kr = (const float4*)Ks[j];
        float4 k0 = kr[0], k1 = kr[1], k2 = kr[2], k3 = kr[3];
        float sc = q0.x * k0.x + q0.y * k0.y + q0.z * k0.z + q0.w * k0.w
                 + q1.x * k1.x + q1.y * k1.y + q1.z * k1.z + q1.w * k1.w
                 + q2.x * k2.x + q2.y * k2.y + q2.z * k2.z + q2.w * k2.w
                 + q3.x * k3.x + q3.y * k3.y + q3.z * k3.z + q3.w * k3.w;
        sc *= 0.25f;   // 1/sqrt(16)
        Ss[b][j] = sc;
        mx = fmaxf(mx, sc);
    }
    float denom = 0.0f;
    float acc[HD];
    #pragma unroll
    for (int d = 0; d < HD; d++) acc[d] = 0.0f;
    #pragma unroll 4
    for (int j = 0; j < BB; j++) {
        float p = cjs[j] * __expf(Ss[b][j] - mx);
        denom += p;
        const float4* vr = (const float4*)Vs[j];
        float4 v0 = vr[0], v1 = vr[1], v2 = vr[2], v3 = vr[3];
        acc[0] += p * v0.x;  acc[1] += p * v0.y;  acc[2] += p * v0.z;  acc[3] += p * v0.w;
        acc[4] += p * v1.x;  acc[5] += p * v1.y;  acc[6] += p * v1.z;  acc[7] += p * v1.w;
        acc[8] += p * v2.x;  acc[9] += p * v2.y;  acc[10] += p * v2.z; acc[11] += p * v2.w;
        acc[12] += p * v3.x; acc[13] += p * v3.y; acc[14] += p * v3.z; acc[15] += p * v3.w;
    }
    float inv = 1.0f / denom;
    float* op = g_O + (b * SS + s) * EE + h * HD;
    #pragma unroll
    for (int d = 0; d < HD; d++) op[d] = acc[d] * inv;
}

// ---------------- 4) seq reduce: G[b] = sum_s fw[s] * O[b,s,:] -------------
__global__ void __launch_bounds__(256) reduce_s(const float* __restrict__ fw) {
    int b = blockIdx.x, e = threadIdx.x;
    __shared__ float fws[SS];
    if (e < SS) fws[e] = fw[e];
    __syncthreads();
    float acc = 0.0f;
    #pragma unroll
    for (int s = 0; s < SS; s++)
        acc += g_O[(b * SS + s) * EE + e] * fws[s];
    g_G[b * EE + e] = acc;
}

// ---------------- 5) head: h = G@Wo^T + sfw*bo + fb; logits; log_softmax ---
__global__ void __launch_bounds__(256) head_kernel(const float* __restrict__ Wo,
                                                   const float* __restrict__ bo,
                                                   const float* __restrict__ fw,
                                                   const float* __restrict__ fb,
                                                   const float* __restrict__ Hw,
                                                   const float* __restrict__ hb) {
    int b = blockIdx.x;
    __shared__ float Gs[EE];
    __shared__ float hs[EE];
    __shared__ float ls[64];
    __shared__ float sfw_sh;
    int tid = threadIdx.x;
    Gs[tid] = g_G[b * EE + tid];
    if (tid < 32) {
        float v = fw[tid];
        #pragma unroll
        for (int o = 16; o > 0; o >>= 1) v += __shfl_xor_sync(0xffffffffu, v, o);
        if (tid == 0) sfw_sh = v;
    }
    __syncthreads();
    int w = tid >> 5, lane = tid & 31;
    float fb0 = fb[0];
    // h rows (256): warp w handles rows [w*32, w*32+32)
    for (int rr = 0; rr < 32; rr++) {
        int r = w * 32 + rr;
        const float* wrow = Wo + r * EE;
        float p = 0.0f;
        #pragma unroll
        for (int k = lane; k < EE; k += 32) p += Gs[k] * wrow[k];
        #pragma unroll
        for (int o = 16; o > 0; o >>= 1) p += __shfl_down_sync(0xffffffffu, p, o);
        if (lane == 0) hs[r] = p + sfw_sh * bo[r] + fb0;
    }
    __syncthreads();
    // logits (46 rows)
    for (int r = w; r < KC; r += 8) {
        const float* hr = Hw + r * EE;
        float p = 0.0f;
        #pragma unroll
        for (int k = lane; k < EE; k += 32) p += hs[k] * hr[k];
        #pragma unroll
        for (int o = 16; o > 0; o >>= 1) p += __shfl_down_sync(0xffffffffu, p, o);
        if (lane == 0) ls[r] = p + hb[r];
    }
    __syncthreads();
    // log_softmax over 46 (warp 0)
    if (w == 0) {
        float v1 = (lane < KC) ? ls[lane] : -1e30f;
        float v2 = (lane + 32 < KC) ? ls[lane + 32] : -1e30f;
        float mx = fmaxf(v1, v2);
        #pragma unroll
        for (int o = 16; o > 0; o >>= 1) mx = fmaxf(mx, __shfl_xor_sync(0xffffffffu, mx, o));
        float se = ((lane < KC) ? __expf(v1 - mx) : 0.0f)
                 + ((lane + 32 < KC) ? __expf(v2 - mx) : 0.0f);
        #pragma unroll
        for (int o = 16; o > 0; o >>= 1) se += __shfl_xor_sync(0xffffffffu, se, o);
        float lse = mx + logf(se);
        if (lane < KC) g_logprob[b * KC + lane] = v1 - lse;
        if (lane + 32 < KC) g_logprob[b * KC + lane + 32] = v2 - lse;
    }
}

// ---------------- 6) loss: class counts, inverse-freq weights, weighted CE -
__global__ void __launch_bounds__(512) loss_kernel(const int* __restrict__ labels0,
                                                   float* __restrict__ out) {
    __shared__ int counts[KC];
    __shared__ float rn[16], rd[16];
    int tid = threadIdx.x;
    if (tid < KC) counts[tid] = 0;
    __syncthreads();
    int i = g_i[tid], j = g_j[tid];
    float valid = g_valid[tid];
    int a = labels0[i], c = labels0[j];
    int y;
    if (a == c) y = 0;
    else {
        int lo = min(a, c), hi = max(a, c);
        y = 1 + lo * 9 - (lo * (lo - 1)) / 2 + (hi - lo - 1);
    }
    if (valid > 0.0f) atomicAdd(&counts[y], 1);
    __syncthreads();
    float cw = counts[y] > 0 ? 1.0f / (float)counts[y] : 0.0f;
    float wy = cw * valid;
    float nll = -g_logprob[i * KC + y];
    float num = wy * nll, den = wy;
    int lane = tid & 31, w = tid >> 5;
    #pragma unroll
    for (int o = 16; o > 0; o >>= 1) {
        num += __shfl_down_sync(0xffffffffu, num, o);
        den += __shfl_down_sync(0xffffffffu, den, o);
    }
    if (lane == 0) { rn[w] = num; rd[w] = den; }
    __syncthreads();
    if (tid < 16) {
        num = rn[tid]; den = rd[tid];
        #pragma unroll
        for (int o = 8; o > 0; o >>= 1) {
            num += __shfl_down_sync(0xffffu, num, o);
            den += __shfl_down_sync(0xffffu, den, o);
        }
        if (tid == 0) out[0] = num / den;
    }
}

// ---------------------------------------------------------------------------
extern "C" void kernel_launch(void* const* d_in, const int* in_sizes, int n_in,
                              void* d_out, int out_size) {
    const float* feat    = (const float*)d_in[0];
    const int*   labels0 = (const int*)d_in[1];
    const int*   labels1 = (const int*)d_in[2];
    const float* ipw     = (const float*)d_in[3];
    const float* ipb     = (const float*)d_in[4];
    const float* opw     = (const float*)d_in[5];
    const float* opb     = (const float*)d_in[6];
    const float* fw      = (const float*)d_in[7];
    const float* fbv     = (const float*)d_in[8];
    const float* hw      = (const float*)d_in[9];
    const float* hbv     = (const float*)d_in[10];
    float* out = (float*)d_out;

    pair_setup<<<1, 256>>>(labels1);
    dim3 g(MROWS / BM, NCOLS / BN);          // 32 x 12
    qkv_gemm<<<g, 256>>>(feat, ipw, ipb);
    attn_kernel<<<SS * HH, 64>>>();          // 512 blocks
    reduce_s<<<BB, 256>>>(fw);
    head_kernel<<<BB, 256>>>(opw, opb, fw, fbv, hw, hbv);
    loss_kernel<<<1, 512>>>(labels0, out);
}